// round 13
// baseline (speedup 1.0000x reference)
#include <cuda_runtime.h>
#include <cstdint>

#define NUM_CLASSES 601
#define OUT_DIM     27
#define TAB_ELEMS   (NUM_CLASSES * OUT_DIM)            // 16227 floats = 64908 B
#define TAB_F4      ((TAB_ELEMS + 3) / 4)              // 4057 float4
#define GATHER_BLOCKS  296                             // 2 per SM (148 SMs)
#define GATHER_THREADS 1024
#define SMEM_BYTES  (TAB_F4 * 16)                      // 64912 B dynamic smem

// Softmax table in global (padded to float4 multiple for vector copy).
__device__ float4 g_tab4[TAB_F4];

// One block per class row; lane j computes exp, warp-reduce, write row (stride 27).
__global__ void build_probs_kernel(const float* __restrict__ W) {
    int r = blockIdx.x;
    int l = threadIdx.x;
    float e = 0.0f;
    if (l < OUT_DIM) e = expf(W[r * OUT_DIM + l]);
    float s = e;
    #pragma unroll
    for (int o = 16; o; o >>= 1) s += __shfl_xor_sync(0xffffffffu, s, o);
    float* tab = (float*)g_tab4;
    if (l < OUT_DIM) tab[r * OUT_DIM + l] = e / s;
}

// Grid-stride gather, one float4 of output per thread per iteration.
// Table in dynamic smem. Per 16B out: 1 magic-div, 2 idx LDG (L1-hot),
// 4 LDS (bank stride 4 within a row segment -> conflict ~2), 1 STG.128.
__global__ void __launch_bounds__(GATHER_THREADS) gather_kernel(
        const int* __restrict__ idx, float4* __restrict__ out4,
        unsigned n4, unsigned nrows) {
    extern __shared__ float s_tab[];

    // Cooperative vectorized table copy into smem.
    {
        const float4* __restrict__ src = g_tab4;
        float4* dst = (float4*)s_tab;
        for (int i = threadIdx.x; i < TAB_F4; i += GATHER_THREADS)
            dst[i] = src[i];
    }
    __syncthreads();

    unsigned tid      = blockIdx.x * GATHER_THREADS + threadIdx.x;
    unsigned nthreads = gridDim.x * GATHER_THREADS;

    for (unsigned t = tid; t < n4; t += nthreads) {
        unsigned base = t * 4u;
        unsigned row  = base / 27u;            // single magic-multiply
        unsigned col  = base - row * 27u;

        int b0 = __ldg(&idx[row]);
        unsigned rown = row + 1u;
        if (rown >= nrows) rown = nrows - 1u;  // clamp tail
        int b1 = __ldg(&idx[rown]);

        const float* __restrict__ r0 = s_tab + (unsigned)b0 * 27u;
        const float* __restrict__ r1 = s_tab + (unsigned)b1 * 27u;

        float v[4];
        #pragma unroll
        for (int k = 0; k < 4; k++) {
            unsigned c = col + (unsigned)k;
            const float* p = (c < 27u) ? (r0 + c) : (r1 + (c - 27u));
            v[k] = *p;                          // LDS (predicated addr select)
        }
        float4 o;
        o.x = v[0]; o.y = v[1]; o.z = v[2]; o.w = v[3];
        __stcs(&out4[t], o);                   // one STG.128, coalesced
    }
}

extern "C" void kernel_launch(void* const* d_in, const int* in_sizes, int n_in,
                              void* d_out, int out_size) {
    // Inputs: bigram_idx (int32, BATCH), W (float32, 601*27). Identify W by size.
    const int*   idx = (const int*)d_in[0];
    const float* W   = (const float*)d_in[1];
    int idx_n = in_sizes[0];
    if (n_in >= 2 && in_sizes[0] == TAB_ELEMS) {
        W     = (const float*)d_in[0];
        idx   = (const int*)d_in[1];
        idx_n = in_sizes[1];
    }
    float* out = (float*)d_out;

    // Allow >48KB dynamic smem (idempotent; host-side, not a stream op).
    static int attr_done = 0;
    if (!attr_done) {
        cudaFuncSetAttribute(gather_kernel,
                             cudaFuncAttributeMaxDynamicSharedMemorySize,
                             SMEM_BYTES);
        attr_done = 1;
    }

    // 1) 601-row softmax table.
    build_probs_kernel<<<NUM_CLASSES, 32>>>(W);

    // 2) smem-table gather, float4 per thread, grid-stride.
    unsigned n4 = (unsigned)(out_size / 4);
    gather_kernel<<<GATHER_BLOCKS, GATHER_THREADS, SMEM_BYTES>>>(
        idx, (float4*)out, n4, (unsigned)idx_n);
}